// round 1
// baseline (speedup 1.0000x reference)
#include <cuda_runtime.h>
#include <math.h>

#define BATCH 256
#define SEQ   720
#define CH    321
#define CUTF  200
#define FOUT  400

// ---------------- scratch (__device__ globals, no allocation) ----------------
__device__ float d_Ecos[CUTF * SEQ];          // rfft cos table  [f][t]
__device__ float d_Esin[CUTF * SEQ];          // rfft sin table  [f][t]
__device__ float d_Fc[SEQ * FOUT];            // irfft cos coef  [t'][k] (scaled)
__device__ float d_Fs[SEQ * FOUT];            // irfft -sin coef [t'][k] (scaled)
__device__ float d_mean[BATCH * CH];
__device__ float d_stdev[BATCH * CH];
__device__ float d_invstd[BATCH * CH];
__device__ float d_xnT[(size_t)CH * SEQ * BATCH];   // [c][t][b]; reused for irfft output
__device__ float d_Xre[(size_t)CH * CUTF * BATCH];  // [c][f][b]
__device__ float d_Xim[(size_t)CH * CUTF * BATCH];
__device__ float d_Ore[(size_t)CH * FOUT * BATCH];  // [c][o][b]
__device__ float d_Oim[(size_t)CH * FOUT * BATCH];

// ---------------- twiddle tables (exact integer phase reduction) -------------
__global__ void k_init_tables() {
    int idx = blockIdx.x * 256 + threadIdx.x;
    if (idx < CUTF * SEQ) {
        int f = idx / SEQ, t = idx - f * SEQ;
        int r = (f * t) % SEQ;                    // theta/pi = f*t/360, reduce mod 720
        float s, c;
        sincospif((float)r * (1.0f / 360.0f), &s, &c);
        d_Ecos[idx] = c;
        d_Esin[idx] = s;
    }
    if (idx < SEQ * FOUT) {
        int tp = idx / FOUT, k = idx - tp * FOUT;
        int t = SEQ + tp;                          // actual output time in [720,1440)
        int m = (k * t) % 1440;                    // theta/pi = k*t/720, reduce mod 1440
        float s, c;
        sincospif((float)m * (1.0f / 720.0f), &s, &c);
        // y[t] * LENGTH_RATIO = (1/720)*ReF0 + (1/360)*sum_{k>=1}(ReFk cos - ImFk sin)
        d_Fc[idx] = (k == 0) ? (1.0f / 720.0f) : (c * (1.0f / 360.0f));
        d_Fs[idx] = (k == 0) ? 0.0f : (-s * (1.0f / 360.0f));
    }
}

// ---------------- per-(b,c) mean / stdev (ddof=1) ----------------------------
__global__ void k_stats(const float* __restrict__ x) {
    int c = blockIdx.x * 256 + threadIdx.x;
    int b = blockIdx.y;
    if (c >= CH) return;
    const float* p = x + (size_t)b * SEQ * CH + c;
    float s = 0.f, ss = 0.f;
    for (int t = 0; t < SEQ; t++) {
        float v = p[(size_t)t * CH];
        s += v;
        ss += v * v;
    }
    float mean = s * (1.0f / SEQ);
    float var = (ss - s * mean) * (1.0f / (SEQ - 1));
    float sd = sqrtf(var + 1e-5f);
    d_mean[b * CH + c] = mean;
    d_stdev[b * CH + c] = sd;
    d_invstd[b * CH + c] = 1.0f / sd;
}

// ---------------- transpose in: [b][t][c] -> [c][t][b], normalized -----------
__global__ void k_transpose_in(const float* __restrict__ x) {
    __shared__ float sm[32][33];
    int t = blockIdx.z;
    int cb = blockIdx.x * 32, bb = blockIdx.y * 32;
    int tx = threadIdx.x, ty = threadIdx.y;
    int c = cb + tx;
#pragma unroll
    for (int i = 0; i < 4; i++) {
        int b = bb + ty + i * 8;
        float v = 0.f;
        if (c < CH)
            v = (x[(size_t)b * (SEQ * CH) + t * CH + c] - d_mean[b * CH + c]) * d_invstd[b * CH + c];
        sm[ty + i * 8][tx] = v;   // sm[b_local][c_local]
    }
    __syncthreads();
#pragma unroll
    for (int i = 0; i < 4; i++) {
        int cc = cb + ty + i * 8;
        if (cc < CH)
            d_xnT[(size_t)cc * (SEQ * BATCH) + t * BATCH + bb + tx] = sm[tx][ty + i * 8];
    }
}

// ---------------- stage 2: DFT  (per channel, M=200 x2, N=256, K=720) --------
__global__ __launch_bounds__(256) void k_dft() {
    const int c = blockIdx.z;
    const int fBase = blockIdx.y * 64;
    const int bBase = blockIdx.x * 64;
    __shared__ float sC[16][64], sS[16][64], sB[16][64];
    float accR[4][4] = {}, accI[4][4] = {};
    int tid = threadIdx.x;
    int tm = (tid >> 4) * 4, tn = (tid & 15) * 4;
    const float* xn = d_xnT + (size_t)c * (SEQ * BATCH);
    int la_m = tid >> 2, la_k = (tid & 3) * 4;
    int lb_k = tid >> 4, lb_n = (tid & 15) * 4;

    for (int k0 = 0; k0 < SEQ; k0 += 16) {
        float4 vc = {0, 0, 0, 0}, vs = {0, 0, 0, 0};
        int f = fBase + la_m;
        if (f < CUTF) {
            vc = *(const float4*)(d_Ecos + f * SEQ + k0 + la_k);
            vs = *(const float4*)(d_Esin + f * SEQ + k0 + la_k);
        }
        sC[la_k + 0][la_m] = vc.x; sC[la_k + 1][la_m] = vc.y;
        sC[la_k + 2][la_m] = vc.z; sC[la_k + 3][la_m] = vc.w;
        sS[la_k + 0][la_m] = vs.x; sS[la_k + 1][la_m] = vs.y;
        sS[la_k + 2][la_m] = vs.z; sS[la_k + 3][la_m] = vs.w;
        *(float4*)&sB[lb_k][lb_n] =
            *(const float4*)(xn + (size_t)(k0 + lb_k) * BATCH + bBase + lb_n);
        __syncthreads();
#pragma unroll
        for (int kk = 0; kk < 16; kk++) {
            float ar[4], ai[4], bv[4];
#pragma unroll
            for (int i = 0; i < 4; i++) { ar[i] = sC[kk][tm + i]; ai[i] = sS[kk][tm + i]; }
            float4 b4 = *(float4*)&sB[kk][tn];
            bv[0] = b4.x; bv[1] = b4.y; bv[2] = b4.z; bv[3] = b4.w;
#pragma unroll
            for (int i = 0; i < 4; i++)
#pragma unroll
                for (int j = 0; j < 4; j++) {
                    accR[i][j] += ar[i] * bv[j];
                    accI[i][j] -= ai[i] * bv[j];   // X = sum x*(cos - i sin)
                }
        }
        __syncthreads();
    }
    float* Xr = d_Xre + (size_t)c * CUTF * BATCH;
    float* Xi = d_Xim + (size_t)c * CUTF * BATCH;
#pragma unroll
    for (int i = 0; i < 4; i++) {
        int f = fBase + tm + i;
        if (f < CUTF) {
            *(float4*)(Xr + f * BATCH + bBase + tn) =
                make_float4(accR[i][0], accR[i][1], accR[i][2], accR[i][3]);
            *(float4*)(Xi + f * BATCH + bBase + tn) =
                make_float4(accI[i][0], accI[i][1], accI[i][2], accI[i][3]);
        }
    }
}

// ---------------- stage 3: complex mixer (per channel, 400x256x200) ----------
__global__ __launch_bounds__(256) void k_cmul(const float* __restrict__ Wr,
                                              const float* __restrict__ Wi,
                                              const float* __restrict__ br,
                                              const float* __restrict__ bi) {
    const int c = blockIdx.z;
    const int oBase = blockIdx.y * 64;
    const int bBase = blockIdx.x * 64;
    __shared__ float sWr[8][64], sWi[8][64], sXr[8][64], sXi[8][64];
    float accR[4][4] = {}, accI[4][4] = {};
    int tid = threadIdx.x;
    int tm = (tid >> 4) * 4, tn = (tid & 15) * 4;
    const float* wrp = Wr + (size_t)c * FOUT * CUTF;
    const float* wip = Wi + (size_t)c * FOUT * CUTF;
    const float* xrp = d_Xre + (size_t)c * CUTF * BATCH;
    const float* xip = d_Xim + (size_t)c * CUTF * BATCH;
    int la_m = tid >> 2, la_k = (tid & 3) * 2;
    int lb_k = tid >> 5, lb_n = (tid & 31) * 2;

    for (int k0 = 0; k0 < CUTF; k0 += 8) {
        int o = oBase + la_m;
        float2 v1 = {0, 0}, v2 = {0, 0};
        if (o < FOUT) {
            v1 = *(const float2*)(wrp + (size_t)o * CUTF + k0 + la_k);
            v2 = *(const float2*)(wip + (size_t)o * CUTF + k0 + la_k);
        }
        sWr[la_k][la_m] = v1.x; sWr[la_k + 1][la_m] = v1.y;
        sWi[la_k][la_m] = v2.x; sWi[la_k + 1][la_m] = v2.y;
        *(float2*)&sXr[lb_k][lb_n] = *(const float2*)(xrp + (k0 + lb_k) * BATCH + bBase + lb_n);
        *(float2*)&sXi[lb_k][lb_n] = *(const float2*)(xip + (k0 + lb_k) * BATCH + bBase + lb_n);
        __syncthreads();
#pragma unroll
        for (int kk = 0; kk < 8; kk++) {
            float wr[4], wi[4], xr[4], xi[4];
#pragma unroll
            for (int i = 0; i < 4; i++) { wr[i] = sWr[kk][tm + i]; wi[i] = sWi[kk][tm + i]; }
            float4 x4 = *(float4*)&sXr[kk][tn];
            xr[0] = x4.x; xr[1] = x4.y; xr[2] = x4.z; xr[3] = x4.w;
            float4 y4 = *(float4*)&sXi[kk][tn];
            xi[0] = y4.x; xi[1] = y4.y; xi[2] = y4.z; xi[3] = y4.w;
#pragma unroll
            for (int i = 0; i < 4; i++)
#pragma unroll
                for (int j = 0; j < 4; j++) {
                    accR[i][j] += wr[i] * xr[j] - wi[i] * xi[j];
                    accI[i][j] += wr[i] * xi[j] + wi[i] * xr[j];
                }
        }
        __syncthreads();
    }
    float* Or = d_Ore + (size_t)c * FOUT * BATCH;
    float* Oi = d_Oim + (size_t)c * FOUT * BATCH;
#pragma unroll
    for (int i = 0; i < 4; i++) {
        int o = oBase + tm + i;
        if (o < FOUT) {
            float vr = br[c * FOUT + o], vi = bi[c * FOUT + o];
            *(float4*)(Or + o * BATCH + bBase + tn) =
                make_float4(accR[i][0] + vr, accR[i][1] + vr, accR[i][2] + vr, accR[i][3] + vr);
            *(float4*)(Oi + o * BATCH + bBase + tn) =
                make_float4(accI[i][0] + vi, accI[i][1] + vi, accI[i][2] + vi, accI[i][3] + vi);
        }
    }
}

// ---------------- stage 4: irfft tail (per channel, 720x256, K=400 re+im) ----
__global__ __launch_bounds__(256) void k_irfft() {
    const int c = blockIdx.z;
    const int tBase = blockIdx.y * 64;
    const int bBase = blockIdx.x * 128;
    __shared__ float sFc[8][64], sFs[8][64], sBr[8][128], sBi[8][128];
    float acc[4][8] = {};
    int tid = threadIdx.x;
    int tm = (tid >> 4) * 4, tn = (tid & 15) * 8;
    const float* orp = d_Ore + (size_t)c * FOUT * BATCH;
    const float* oip = d_Oim + (size_t)c * FOUT * BATCH;
    int la_m = tid >> 2, la_k = (tid & 3) * 2;
    int lb_k = tid >> 5, lb_n = (tid & 31) * 4;

    for (int k0 = 0; k0 < FOUT; k0 += 8) {
        int t = tBase + la_m;
        float2 v1 = {0, 0}, v2 = {0, 0};
        if (t < SEQ) {
            v1 = *(const float2*)(d_Fc + (size_t)t * FOUT + k0 + la_k);
            v2 = *(const float2*)(d_Fs + (size_t)t * FOUT + k0 + la_k);
        }
        sFc[la_k][la_m] = v1.x; sFc[la_k + 1][la_m] = v1.y;
        sFs[la_k][la_m] = v2.x; sFs[la_k + 1][la_m] = v2.y;
        *(float4*)&sBr[lb_k][lb_n] = *(const float4*)(orp + (k0 + lb_k) * BATCH + bBase + lb_n);
        *(float4*)&sBi[lb_k][lb_n] = *(const float4*)(oip + (k0 + lb_k) * BATCH + bBase + lb_n);
        __syncthreads();
#pragma unroll
        for (int kk = 0; kk < 8; kk++) {
            float fc[4], fs[4], bre[8], bim[8];
#pragma unroll
            for (int i = 0; i < 4; i++) { fc[i] = sFc[kk][tm + i]; fs[i] = sFs[kk][tm + i]; }
#pragma unroll
            for (int j = 0; j < 8; j += 4) {
                float4 r4 = *(float4*)&sBr[kk][tn + j];
                bre[j] = r4.x; bre[j + 1] = r4.y; bre[j + 2] = r4.z; bre[j + 3] = r4.w;
                float4 i4 = *(float4*)&sBi[kk][tn + j];
                bim[j] = i4.x; bim[j + 1] = i4.y; bim[j + 2] = i4.z; bim[j + 3] = i4.w;
            }
#pragma unroll
            for (int i = 0; i < 4; i++)
#pragma unroll
                for (int j = 0; j < 8; j++)
                    acc[i][j] += fc[i] * bre[j] + fs[i] * bim[j];
        }
        __syncthreads();
    }
    float* y = d_xnT + (size_t)c * SEQ * BATCH;   // reuse xnT as y[c][t][b]
#pragma unroll
    for (int i = 0; i < 4; i++) {
        int t = tBase + tm + i;
        if (t < SEQ) {
            *(float4*)(y + (size_t)t * BATCH + bBase + tn) =
                make_float4(acc[i][0], acc[i][1], acc[i][2], acc[i][3]);
            *(float4*)(y + (size_t)t * BATCH + bBase + tn + 4) =
                make_float4(acc[i][4], acc[i][5], acc[i][6], acc[i][7]);
        }
    }
}

// ---------------- transpose out: [c][t][b] -> [b][t][c], de-normalize --------
__global__ void k_transpose_out(float* __restrict__ out) {
    __shared__ float sm[32][33];
    int t = blockIdx.z;
    int cb = blockIdx.x * 32, bb = blockIdx.y * 32;
    int tx = threadIdx.x, ty = threadIdx.y;
#pragma unroll
    for (int i = 0; i < 4; i++) {
        int cc = cb + ty + i * 8;
        float v = 0.f;
        if (cc < CH) v = d_xnT[(size_t)cc * (SEQ * BATCH) + t * BATCH + bb + tx];
        sm[ty + i * 8][tx] = v;   // sm[c_local][b_local]
    }
    __syncthreads();
    int c = cb + tx;
#pragma unroll
    for (int i = 0; i < 4; i++) {
        int b = bb + ty + i * 8;
        if (c < CH) {
            float v = sm[tx][ty + i * 8];
            out[(size_t)b * (SEQ * CH) + t * CH + c] = v * d_stdev[b * CH + c] + d_mean[b * CH + c];
        }
    }
}

// ---------------- launch -----------------------------------------------------
extern "C" void kernel_launch(void* const* d_in, const int* in_sizes, int n_in,
                              void* d_out, int out_size) {
    const float* x_enc = (const float*)d_in[0];
    const float* Wr = (const float*)d_in[4];
    const float* Wi = (const float*)d_in[5];
    const float* br = (const float*)d_in[6];
    const float* bi = (const float*)d_in[7];
    float* out = (float*)d_out;

    k_init_tables<<<1125, 256>>>();                         // 288000 threads
    k_stats<<<dim3(2, BATCH), 256>>>(x_enc);
    k_transpose_in<<<dim3(11, 8, SEQ), dim3(32, 8)>>>(x_enc);
    k_dft<<<dim3(4, 4, CH), 256>>>();
    k_cmul<<<dim3(4, 7, CH), 256>>>(Wr, Wi, br, bi);
    k_irfft<<<dim3(2, 12, CH), 256>>>();
    k_transpose_out<<<dim3(11, 8, SEQ), dim3(32, 8)>>>(out);
}